// round 3
// baseline (speedup 1.0000x reference)
#include <cuda_runtime.h>

// R3: projections moved to tensor cores (tf32 mma.sync, 3xTF32 for fp32-class
// accuracy). Attention/copy kernels unchanged from R2 (2830us baseline).

#define B_   2
#define TQ_  2048
#define TP_  2048
#define TKV_ 4096
#define H_   16
#define DK_  64
#define DM_  1024

__device__ float g_Q[(size_t)B_ * H_ * TQ_ * DK_];      // [B,H,TQ,DK]
__device__ float g_attn[(size_t)B_ * TQ_ * DM_];        // [B,TQ,DM]

#define GM 4096
#define GN 1024
#define GK 1024
#define LDK 20   // 16 k-floats + 4 pad (conflict-free fragment LDS)

// ---------------------------------------------------------------------------
// Tensor-core GEMM: C = A @ W^T + bias, 3xTF32.
// 128x128x16 tile, 8 warps (4 m x 2 n), warp tile 32x64 (2 x 8 mma tiles).
// mode 0: Q->g_Q head layout; 1/2: K/V -> d_out cache at t>=TP_; 3: attn->out.
// ---------------------------------------------------------------------------
__device__ __forceinline__ unsigned f2tf32(float x) {
    unsigned u;
    asm("cvt.rna.tf32.f32 %0, %1;" : "=r"(u) : "f"(x));
    return u;
}

#define MMA_TF32(C, A, B)                                                     \
    asm("mma.sync.aligned.m16n8k8.row.col.f32.tf32.tf32.f32 "                 \
        "{%0,%1,%2,%3}, {%4,%5,%6,%7}, {%8,%9}, {%0,%1,%2,%3};"               \
        : "+f"(C[0]), "+f"(C[1]), "+f"(C[2]), "+f"(C[3])                      \
        : "r"(A[0]), "r"(A[1]), "r"(A[2]), "r"(A[3]), "r"(B[0]), "r"(B[1]))

__global__ __launch_bounds__(256)
void gemm_tc_kernel(const float* __restrict__ A, const float* __restrict__ W,
                    const float* __restrict__ bias, float* __restrict__ outb,
                    int mode)
{
    __shared__ float Ab[128][LDK], Al[128][LDK];   // A big / small (tf32)
    __shared__ float Wb[128][LDK], Wl[128][LDK];   // W big / small
    if (mode == 3) A = g_attn;

    const int bm = blockIdx.y * 128;
    const int bn = blockIdx.x * 128;
    const int tid = threadIdx.x;
    const int warp = tid >> 5, lane = tid & 31;
    const int g = lane >> 2, tig = lane & 3;
    const int m0w = (warp & 3) * 32;   // warp row offset in tile
    const int n0w = (warp >> 2) * 64;  // warp col offset in tile

    const int lrow = tid >> 2;         // 0..63 (2 passes of 64 rows)
    const int lk = (tid & 3) * 4;      // k offset (float4)

    float c[2][8][4] = {};

    // prologue prefetch
    float4 pa[2], pw[2];
    #pragma unroll
    for (int p = 0; p < 2; ++p) {
        int r = lrow + p * 64;
        pa[p] = *(const float4*)&A[(size_t)(bm + r) * GK + lk];
        pw[p] = *(const float4*)&W[(size_t)(bn + r) * GK + lk];
    }

    for (int k0 = 0; k0 < GK; k0 += 16) {
        // convert + stage prefetched tile
        #pragma unroll
        for (int p = 0; p < 2; ++p) {
            int r = lrow + p * 64;
            float ax[4] = {pa[p].x, pa[p].y, pa[p].z, pa[p].w};
            float wx[4] = {pw[p].x, pw[p].y, pw[p].z, pw[p].w};
            #pragma unroll
            for (int q = 0; q < 4; ++q) {
                unsigned hb = f2tf32(ax[q]);
                float big = __uint_as_float(hb);
                Ab[r][lk + q] = big;
                Al[r][lk + q] = __uint_as_float(f2tf32(ax[q] - big));
                hb = f2tf32(wx[q]);
                big = __uint_as_float(hb);
                Wb[r][lk + q] = big;
                Wl[r][lk + q] = __uint_as_float(f2tf32(wx[q] - big));
            }
        }
        __syncthreads();

        // prefetch next tile (overlaps with mma phase below)
        if (k0 + 16 < GK) {
            #pragma unroll
            for (int p = 0; p < 2; ++p) {
                int r = lrow + p * 64;
                pa[p] = *(const float4*)&A[(size_t)(bm + r) * GK + k0 + 16 + lk];
                pw[p] = *(const float4*)&W[(size_t)(bn + r) * GK + k0 + 16 + lk];
            }
        }

        #pragma unroll
        for (int ks = 0; ks < 16; ks += 8) {
            unsigned ab[2][4], as[2][4];
            #pragma unroll
            for (int mt = 0; mt < 2; ++mt) {
                int r = m0w + mt * 16 + g;
                ab[mt][0] = __float_as_uint(Ab[r][ks + tig]);
                ab[mt][1] = __float_as_uint(Ab[r + 8][ks + tig]);
                ab[mt][2] = __float_as_uint(Ab[r][ks + tig + 4]);
                ab[mt][3] = __float_as_uint(Ab[r + 8][ks + tig + 4]);
                as[mt][0] = __float_as_uint(Al[r][ks + tig]);
                as[mt][1] = __float_as_uint(Al[r + 8][ks + tig]);
                as[mt][2] = __float_as_uint(Al[r][ks + tig + 4]);
                as[mt][3] = __float_as_uint(Al[r + 8][ks + tig + 4]);
            }
            unsigned bb[8][2], bs[8][2];
            #pragma unroll
            for (int nt = 0; nt < 8; ++nt) {
                int n = n0w + nt * 8 + g;
                bb[nt][0] = __float_as_uint(Wb[n][ks + tig]);
                bb[nt][1] = __float_as_uint(Wb[n][ks + tig + 4]);
                bs[nt][0] = __float_as_uint(Wl[n][ks + tig]);
                bs[nt][1] = __float_as_uint(Wl[n][ks + tig + 4]);
            }
            #pragma unroll
            for (int mt = 0; mt < 2; ++mt)
                #pragma unroll
                for (int nt = 0; nt < 8; ++nt) {
                    MMA_TF32(c[mt][nt], ab[mt], bs[nt]);   // big * small
                    MMA_TF32(c[mt][nt], as[mt], bb[nt]);   // small * big
                    MMA_TF32(c[mt][nt], ab[mt], bb[nt]);   // big * big
                }
        }
        __syncthreads();
    }

    // epilogue scatter
    #pragma unroll
    for (int mt = 0; mt < 2; ++mt) {
        #pragma unroll
        for (int nt = 0; nt < 8; ++nt) {
            #pragma unroll
            for (int fr = 0; fr < 4; ++fr) {
                const int gm = bm + m0w + mt * 16 + g + (fr >> 1) * 8;
                const int gn = bn + n0w + nt * 8 + 2 * tig + (fr & 1);
                float v = c[mt][nt][fr] + bias[gn];
                if (mode == 3) {
                    outb[(size_t)gm * GN + gn] = v;
                } else {
                    const int b = gm >> 11;
                    const int t = gm & (TQ_ - 1);
                    const int h = gn >> 6;
                    const int d = gn & (DK_ - 1);
                    if (mode == 0)
                        g_Q[(((size_t)b * H_ + h) * TQ_ + t) * DK_ + d] = v;
                    else
                        outb[(((size_t)b * H_ + h) * TKV_ + TP_ + t) * DK_ + d] = v;
                }
            }
        }
    }
}

// ---------------------------------------------------------------------------
// Copy past_K / past_V into the d_out KV-cache region (t in [0, TP_))
// ---------------------------------------------------------------------------
__global__ __launch_bounds__(256)
void copy_past_kernel(const float4* __restrict__ pk, const float4* __restrict__ pv,
                      float4* __restrict__ ok, float4* __restrict__ ov)
{
    const int per_chunk = TP_ * DK_ / 4;
    const int dst_chunk = TKV_ * DK_ / 4;
    const size_t total = (size_t)B_ * H_ * per_chunk;
    for (size_t idx = (size_t)blockIdx.x * blockDim.x + threadIdx.x;
         idx < total; idx += (size_t)gridDim.x * blockDim.x) {
        size_t c = idx / per_chunk;
        size_t r = idx - c * per_chunk;
        size_t dst = c * dst_chunk + r;
        ok[dst] = pk[idx];
        ov[dst] = pv[idx];
    }
}

// ---------------------------------------------------------------------------
// Flash attention: 64x64 tiles, online softmax in registers (unchanged)
// ---------------------------------------------------------------------------
#define AT_PAD 72
#define AT_SMEM (4 * 64 * AT_PAD * (int)sizeof(float))

__global__ __launch_bounds__(256, 2)
void attn_kernel(const float* __restrict__ Kc, const float* __restrict__ Vc)
{
    extern __shared__ float smf[];
    float* Qs = smf;
    float* Ks = smf + 64 * AT_PAD;
    float* Vs = smf + 2 * 64 * AT_PAD;
    float* Ps = smf + 3 * 64 * AT_PAD;

    const int tid = threadIdx.x;
    const int tx = tid & 15;
    const int ty = tid >> 4;
    const int i0 = ty * 4;
    const int c0 = tx * 4;
    const int q0 = blockIdx.x * 64;
    const int bh = blockIdx.y;

    {
        const int d4 = (tid >> 4) * 4;
        const int il = tid & 15;
        const float* qbase = g_Q + (size_t)bh * TQ_ * DK_ + (size_t)q0 * DK_;
        #pragma unroll
        for (int p = 0; p < 4; ++p) {
            int i = il + p * 16;
            float4 v = *(const float4*)&qbase[(size_t)i * DK_ + d4];
            Qs[(d4 + 0) * AT_PAD + i] = v.x;
            Qs[(d4 + 1) * AT_PAD + i] = v.y;
            Qs[(d4 + 2) * AT_PAD + i] = v.z;
            Qs[(d4 + 3) * AT_PAD + i] = v.w;
        }
    }

    float o[4][4] = {};
    float m_run[4], l_run[4];
    #pragma unroll
    for (int ii = 0; ii < 4; ++ii) { m_run[ii] = -1e30f; l_run[ii] = 0.f; }

    const float* kbase = Kc + (size_t)bh * TKV_ * DK_;
    const float* vbase = Vc + (size_t)bh * TKV_ * DK_;
    const int kv_len = TP_ + q0 + 64;

    for (int k0 = 0; k0 < kv_len; k0 += 64) {
        __syncthreads();
        {
            const int d4 = (tid >> 4) * 4;
            const int jl = tid & 15;
            #pragma unroll
            for (int p = 0; p < 4; ++p) {
                int j = jl + p * 16;
                float4 v = *(const float4*)&kbase[(size_t)(k0 + j) * DK_ + d4];
                Ks[(d4 + 0) * AT_PAD + j] = v.x;
                Ks[(d4 + 1) * AT_PAD + j] = v.y;
                Ks[(d4 + 2) * AT_PAD + j] = v.z;
                Ks[(d4 + 3) * AT_PAD + j] = v.w;
            }
        }
        {
            const int d4 = (tid & 15) * 4;
            const int jl = tid >> 4;
            #pragma unroll
            for (int p = 0; p < 4; ++p) {
                int j = jl + p * 16;
                float4 v = *(const float4*)&vbase[(size_t)(k0 + j) * DK_ + d4];
                *(float4*)&Vs[j * AT_PAD + d4] = v;
            }
        }
        __syncthreads();

        float s[4][4] = {};
        #pragma unroll 16
        for (int d = 0; d < 64; ++d) {
            float a[4], b[4];
            *(float4*)a = *(const float4*)&Qs[d * AT_PAD + i0];
            *(float4*)b = *(const float4*)&Ks[d * AT_PAD + c0];
            #pragma unroll
            for (int ii = 0; ii < 4; ++ii)
                #pragma unroll
                for (int jj = 0; jj < 4; ++jj)
                    s[ii][jj] = fmaf(a[ii], b[jj], s[ii][jj]);
        }

        const bool need_mask = (k0 + 64 > TP_ + q0);
        #pragma unroll
        for (int ii = 0; ii < 4; ++ii)
            #pragma unroll
            for (int jj = 0; jj < 4; ++jj) {
                float v = s[ii][jj] * 0.125f;
                if (need_mask && (k0 + c0 + jj > TP_ + q0 + i0 + ii)) v = -1e30f;
                s[ii][jj] = v;
            }

        #pragma unroll
        for (int ii = 0; ii < 4; ++ii) {
            float mx = fmaxf(fmaxf(s[ii][0], s[ii][1]), fmaxf(s[ii][2], s[ii][3]));
            #pragma unroll
            for (int off = 8; off >= 1; off >>= 1)
                mx = fmaxf(mx, __shfl_xor_sync(0xffffffffu, mx, off));
            float mnew = fmaxf(m_run[ii], mx);
            float corr = __expf(m_run[ii] - mnew);
            m_run[ii] = mnew;
            float ls = 0.f;
            #pragma unroll
            for (int jj = 0; jj < 4; ++jj) {
                float p = __expf(s[ii][jj] - mnew);
                s[ii][jj] = p;
                ls += p;
            }
            #pragma unroll
            for (int off = 8; off >= 1; off >>= 1)
                ls += __shfl_xor_sync(0xffffffffu, ls, off);
            l_run[ii] = l_run[ii] * corr + ls;
            #pragma unroll
            for (int jj = 0; jj < 4; ++jj) o[ii][jj] *= corr;
        }

        #pragma unroll
        for (int jj = 0; jj < 4; ++jj) {
            const int j = c0 + jj;
            const int sw = j & 60;
            #pragma unroll
            for (int ii = 0; ii < 4; ++ii)
                Ps[j * AT_PAD + ((i0 + ii) ^ sw)] = s[ii][jj];
        }
        __syncthreads();

        #pragma unroll 16
        for (int j = 0; j < 64; ++j) {
            const int sw = j & 60;
            float a[4], b[4];
            *(float4*)a = *(const float4*)&Ps[j * AT_PAD + (i0 ^ sw)];
            *(float4*)b = *(const float4*)&Vs[j * AT_PAD + c0];
            #pragma unroll
            for (int ii = 0; ii < 4; ++ii)
                #pragma unroll
                for (int jj = 0; jj < 4; ++jj)
                    o[ii][jj] = fmaf(a[ii], b[jj], o[ii][jj]);
        }
    }

    const int bb = bh >> 4;
    const int hh = bh & 15;
    #pragma unroll
    for (int ii = 0; ii < 4; ++ii) {
        float inv = 1.f / l_run[ii];
        size_t base = ((size_t)bb * TQ_ + q0 + i0 + ii) * DM_ + hh * DK_ + c0;
        float4 r;
        r.x = o[ii][0] * inv; r.y = o[ii][1] * inv;
        r.z = o[ii][2] * inv; r.w = o[ii][3] * inv;
        *(float4*)&g_attn[base] = r;
    }
}

// ---------------------------------------------------------------------------
extern "C" void kernel_launch(void* const* d_in, const int* in_sizes, int n_in,
                              void* d_out, int out_size)
{
    const float* query = (const float*)d_in[0];
    const float* key   = (const float*)d_in[1];
    const float* value = (const float*)d_in[2];
    const float* pastK = (const float*)d_in[3];
    const float* pastV = (const float*)d_in[4];
    const float* Wq = (const float*)d_in[6];
    const float* bq = (const float*)d_in[7];
    const float* Wk = (const float*)d_in[8];
    const float* bk = (const float*)d_in[9];
    const float* Wv = (const float*)d_in[10];
    const float* bv = (const float*)d_in[11];
    const float* Wo = (const float*)d_in[12];
    const float* bo = (const float*)d_in[13];

    float* out  = (float*)d_out;
    float* outK = out + (size_t)B_ * TQ_ * DM_;
    float* outV = outK + (size_t)B_ * H_ * TKV_ * DK_;

    cudaFuncSetAttribute(attn_kernel,
                         cudaFuncAttributeMaxDynamicSharedMemorySize, AT_SMEM);

    dim3 gg(GN / 128, GM / 128);
    gemm_tc_kernel<<<gg, 256>>>(query, Wq, bq, nullptr, 0);
    gemm_tc_kernel<<<gg, 256>>>(key,   Wk, bk, outK,   1);
    gemm_tc_kernel<<<gg, 256>>>(value, Wv, bv, outV,   2);
    copy_past_kernel<<<1024, 256>>>((const float4*)pastK, (const float4*)pastV,
                                    (float4*)outK, (float4*)outV);
    attn_kernel<<<dim3(TQ_ / 64, B_ * H_), 256, AT_SMEM>>>(outK, outV);
    gemm_tc_kernel<<<gg, 256>>>(nullptr, Wo, bo, out, 3);
}

// round 6
// speedup vs baseline: 2.4075x; 2.4075x over previous
#include <cuda_runtime.h>
#include <cuda_bf16.h>
#include <cstdint>

// R6: tcgen05 is NOT available (harness compiles for sm_100, not sm_100a —
// proven by R5 ptxas errors). Pivot: legacy mma.sync m16n8k16 bf16 with
// hh+hl+lh 3-term split (rel err ~2^-16) for BOTH projections and attention.

#define B_   2
#define TQ_  2048
#define TP_  2048
#define TKV_ 4096
#define H_   16
#define DK_  64
#define DM_  1024

__device__ float g_Q[(size_t)B_ * H_ * TQ_ * DK_];      // [B,H,TQ,DK]
__device__ float g_attn[(size_t)B_ * TQ_ * DM_];        // [B,TQ,DM]

// ---------------------------------------------------------------------------
__device__ __forceinline__ uint32_t bfpack(float a, float b) {
    __nv_bfloat162 t(__float2bfloat16_rn(a), __float2bfloat16_rn(b)); // .x = low
    return *reinterpret_cast<uint32_t*>(&t);
}
__device__ __forceinline__ float bfres(float x) {
    return x - __bfloat162float(__float2bfloat16_rn(x));
}
__device__ __forceinline__ float bflo_f(uint32_t u) {  // float of low bf16 half
    return __uint_as_float(u << 16);
}
__device__ __forceinline__ float bfhi_f(uint32_t u) {  // float of high bf16 half
    return __uint_as_float(u & 0xffff0000u);
}

#define MMA_BF16(C, A, B0, B1)                                                \
    asm volatile("mma.sync.aligned.m16n8k16.row.col.f32.bf16.bf16.f32 "       \
        "{%0,%1,%2,%3}, {%4,%5,%6,%7}, {%8,%9}, {%0,%1,%2,%3};"               \
        : "+f"((C)[0]), "+f"((C)[1]), "+f"((C)[2]), "+f"((C)[3])              \
        : "r"((A)[0]), "r"((A)[1]), "r"((A)[2]), "r"((A)[3]),                 \
          "r"(B0), "r"(B1))

// ---------------------------------------------------------------------------
// GEMM: C[4096,1024] = A @ W^T + bias (bf16x3). 128x128x16 chunks, 8 warps
// (4m x 2n), warp tile 32x64. mode 0: Q scatter; 1/2: K/V cache; 3: attn out.
// ---------------------------------------------------------------------------
#define LDB 24   // bf16 row stride (16 data + 8 pad) -> conflict-free frags

__global__ __launch_bounds__(256)
void gemm_mma_kernel(const float* __restrict__ A, const float* __restrict__ W,
                     const float* __restrict__ bias, float* __restrict__ outb,
                     int mode)
{
    __shared__ __nv_bfloat16 Ah[128 * LDB], Al[128 * LDB];
    __shared__ __nv_bfloat16 Wh[128 * LDB], Wl[128 * LDB];
    if (mode == 3) A = g_attn;

    const int tid = threadIdx.x;
    const int warp = tid >> 5, lane = tid & 31;
    const int g = lane >> 2, tig = lane & 3;
    const int bm = blockIdx.y * 128, bn = blockIdx.x * 128;
    const int m0w = (warp & 3) * 32, n0w = (warp >> 2) * 64;
    const int lrow = tid >> 2, lk = (tid & 3) * 4;

    float c[2][8][4] = {};

    float4 pa[2], pw[2];
    #pragma unroll
    for (int p = 0; p < 2; ++p) {
        pa[p] = *(const float4*)&A[(size_t)(bm + lrow + p * 64) * 1024 + lk];
        pw[p] = *(const float4*)&W[(size_t)(bn + lrow + p * 64) * 1024 + lk];
    }

    for (int k0 = 0; k0 < 1024; k0 += 16) {
        #pragma unroll
        for (int p = 0; p < 2; ++p) {
            const int r = lrow + p * 64;
            *(uint32_t*)&Ah[r * LDB + lk]     = bfpack(pa[p].x, pa[p].y);
            *(uint32_t*)&Ah[r * LDB + lk + 2] = bfpack(pa[p].z, pa[p].w);
            *(uint32_t*)&Al[r * LDB + lk]     = bfpack(bfres(pa[p].x), bfres(pa[p].y));
            *(uint32_t*)&Al[r * LDB + lk + 2] = bfpack(bfres(pa[p].z), bfres(pa[p].w));
            *(uint32_t*)&Wh[r * LDB + lk]     = bfpack(pw[p].x, pw[p].y);
            *(uint32_t*)&Wh[r * LDB + lk + 2] = bfpack(pw[p].z, pw[p].w);
            *(uint32_t*)&Wl[r * LDB + lk]     = bfpack(bfres(pw[p].x), bfres(pw[p].y));
            *(uint32_t*)&Wl[r * LDB + lk + 2] = bfpack(bfres(pw[p].z), bfres(pw[p].w));
        }
        __syncthreads();

        if (k0 + 16 < 1024) {
            #pragma unroll
            for (int p = 0; p < 2; ++p) {
                pa[p] = *(const float4*)&A[(size_t)(bm + lrow + p * 64) * 1024 + k0 + 16 + lk];
                pw[p] = *(const float4*)&W[(size_t)(bn + lrow + p * 64) * 1024 + k0 + 16 + lk];
            }
        }

        uint32_t ah[2][4], al_[2][4];
        #pragma unroll
        for (int mt = 0; mt < 2; ++mt) {
            const int r = m0w + mt * 16 + g;
            ah[mt][0]  = *(const uint32_t*)&Ah[r * LDB + 2 * tig];
            ah[mt][1]  = *(const uint32_t*)&Ah[(r + 8) * LDB + 2 * tig];
            ah[mt][2]  = *(const uint32_t*)&Ah[r * LDB + 8 + 2 * tig];
            ah[mt][3]  = *(const uint32_t*)&Ah[(r + 8) * LDB + 8 + 2 * tig];
            al_[mt][0] = *(const uint32_t*)&Al[r * LDB + 2 * tig];
            al_[mt][1] = *(const uint32_t*)&Al[(r + 8) * LDB + 2 * tig];
            al_[mt][2] = *(const uint32_t*)&Al[r * LDB + 8 + 2 * tig];
            al_[mt][3] = *(const uint32_t*)&Al[(r + 8) * LDB + 8 + 2 * tig];
        }
        #pragma unroll
        for (int nt = 0; nt < 8; ++nt) {
            const int n = n0w + nt * 8 + g;
            const uint32_t bh0 = *(const uint32_t*)&Wh[n * LDB + 2 * tig];
            const uint32_t bh1 = *(const uint32_t*)&Wh[n * LDB + 8 + 2 * tig];
            const uint32_t bl0 = *(const uint32_t*)&Wl[n * LDB + 2 * tig];
            const uint32_t bl1 = *(const uint32_t*)&Wl[n * LDB + 8 + 2 * tig];
            #pragma unroll
            for (int mt = 0; mt < 2; ++mt) {
                MMA_BF16(c[mt][nt], ah[mt], bh0, bh1);   // hh
                MMA_BF16(c[mt][nt], ah[mt], bl0, bl1);   // hl
                MMA_BF16(c[mt][nt], al_[mt], bh0, bh1);  // lh
            }
        }
        __syncthreads();
    }

    // epilogue scatter (C fragment: c0=(g,2tig) c1=+1 c2,c3=row g+8)
    #pragma unroll
    for (int mt = 0; mt < 2; ++mt)
        #pragma unroll
        for (int nt = 0; nt < 8; ++nt)
            #pragma unroll
            for (int fr = 0; fr < 4; ++fr) {
                const int gm = bm + m0w + mt * 16 + g + (fr >> 1) * 8;
                const int gn = bn + n0w + nt * 8 + 2 * tig + (fr & 1);
                float v = c[mt][nt][fr] + bias[gn];
                if (mode == 3) {
                    outb[(size_t)gm * 1024 + gn] = v;
                } else {
                    const int b = gm >> 11, t = gm & (TQ_ - 1);
                    const int h = gn >> 6, d = gn & (DK_ - 1);
                    if (mode == 0)
                        g_Q[(((size_t)b * H_ + h) * TQ_ + t) * DK_ + d] = v;
                    else
                        outb[(((size_t)b * H_ + h) * TKV_ + TP_ + t) * DK_ + d] = v;
                }
            }
}

// ---------------------------------------------------------------------------
// Copy past_K / past_V into the d_out KV-cache region (t in [0, TP_))
// ---------------------------------------------------------------------------
__global__ __launch_bounds__(256)
void copy_past_kernel(const float4* __restrict__ pk, const float4* __restrict__ pv,
                      float4* __restrict__ ok, float4* __restrict__ ov)
{
    const int per_chunk = TP_ * DK_ / 4;
    const int dst_chunk = TKV_ * DK_ / 4;
    const size_t total = (size_t)B_ * H_ * per_chunk;
    for (size_t idx = (size_t)blockIdx.x * blockDim.x + threadIdx.x;
         idx < total; idx += (size_t)gridDim.x * blockDim.x) {
        size_t c = idx / per_chunk;
        size_t r = idx - c * per_chunk;
        ok[c * dst_chunk + r] = pk[idx];
        ov[c * dst_chunk + r] = pv[idx];
    }
}

// ---------------------------------------------------------------------------
// Flash attention with bf16x3 mma. CTA = 128 threads (4 warps), Q tile 64,
// KV tile 64. Warp w owns q-rows 16w..16w+15, full 64-kv / 64-d extent, so
// softmax reduces inside a 4-lane shfl group. P fragments for P@V are packed
// straight from S accumulator fragments (no smem round trip), hi/lo split.
// smem strides: 72 bf16 (36 words) everywhere -> conflict-free b32 frag LDS.
// ---------------------------------------------------------------------------
#define AST 72                               // bf16 row stride
#define ATO (64 * AST)                       // one 64-row plane, bf16 elems
#define AT_SMEM (6 * ATO * 2)                // Qh Ql Kh Kl Vth Vtl = 55296 B

__global__ __launch_bounds__(128)
void attn_mma_kernel(const float* __restrict__ Kc, const float* __restrict__ Vc)
{
    extern __shared__ __nv_bfloat16 smb[];
    __nv_bfloat16* Qh  = smb;
    __nv_bfloat16* Ql  = smb + ATO;
    __nv_bfloat16* Kh  = smb + 2 * ATO;
    __nv_bfloat16* Kl  = smb + 3 * ATO;
    __nv_bfloat16* Vth = smb + 4 * ATO;      // transposed: [d][kv]
    __nv_bfloat16* Vtl = smb + 5 * ATO;

    const int tid = threadIdx.x;
    const int warp = tid >> 5, lane = tid & 31;
    const int g = lane >> 2, tig = lane & 3;
    const int q0 = blockIdx.x * 64;
    const int bh = blockIdx.y;

    // ---- load Q tile (rows q0..q0+63), split hi/lo ----
    {
        const int row = tid >> 4, d4 = (tid & 15) * 4;
        const float* qb = g_Q + (size_t)bh * TQ_ * DK_ + (size_t)q0 * DK_;
        #pragma unroll
        for (int p = 0; p < 8; ++p) {
            const int r = row + p * 8;
            float4 v = *(const float4*)&qb[(size_t)r * DK_ + d4];
            *(uint32_t*)&Qh[r * AST + d4]     = bfpack(v.x, v.y);
            *(uint32_t*)&Qh[r * AST + d4 + 2] = bfpack(v.z, v.w);
            *(uint32_t*)&Ql[r * AST + d4]     = bfpack(bfres(v.x), bfres(v.y));
            *(uint32_t*)&Ql[r * AST + d4 + 2] = bfpack(bfres(v.z), bfres(v.w));
        }
    }

    float S[8][4];
    float O[8][4] = {};
    float m0 = -1e30f, m1 = -1e30f, l0 = 0.f, l1 = 0.f;

    const float* kb = Kc + (size_t)bh * TKV_ * DK_;
    const float* vb = Vc + (size_t)bh * TKV_ * DK_;
    const int kv_len = TP_ + q0 + 64;
    const int r0 = 16 * warp + g;            // this lane's first q-row (local)

    for (int k0 = 0; k0 < kv_len; k0 += 64) {
        __syncthreads();
        // K tile natural [kv][d]
        {
            const int row = tid >> 4, d4 = (tid & 15) * 4;
            #pragma unroll
            for (int p = 0; p < 8; ++p) {
                const int r = row + p * 8;
                float4 v = *(const float4*)&kb[(size_t)(k0 + r) * DK_ + d4];
                *(uint32_t*)&Kh[r * AST + d4]     = bfpack(v.x, v.y);
                *(uint32_t*)&Kh[r * AST + d4 + 2] = bfpack(v.z, v.w);
                *(uint32_t*)&Kl[r * AST + d4]     = bfpack(bfres(v.x), bfres(v.y));
                *(uint32_t*)&Kl[r * AST + d4 + 2] = bfpack(bfres(v.z), bfres(v.w));
            }
        }
        // V tile transposed [d][kv], kv-adjacent pairs packed in one b32
        {
            const int j0 = (tid >> 4) * 2, d4 = (tid & 15) * 4;
            #pragma unroll
            for (int p = 0; p < 4; ++p) {
                const int j = j0 + p * 16;
                float4 v0 = *(const float4*)&vb[(size_t)(k0 + j) * DK_ + d4];
                float4 v1 = *(const float4*)&vb[(size_t)(k0 + j + 1) * DK_ + d4];
                const float a0[4] = {v0.x, v0.y, v0.z, v0.w};
                const float a1[4] = {v1.x, v1.y, v1.z, v1.w};
                #pragma unroll
                for (int q = 0; q < 4; ++q) {
                    *(uint32_t*)&Vth[(d4 + q) * AST + j] = bfpack(a0[q], a1[q]);
                    *(uint32_t*)&Vtl[(d4 + q) * AST + j] =
                        bfpack(bfres(a0[q]), bfres(a1[q]));
                }
            }
        }
        __syncthreads();

        // ---- S = Q K^T ----
        #pragma unroll
        for (int t = 0; t < 8; ++t)
            #pragma unroll
            for (int fr = 0; fr < 4; ++fr) S[t][fr] = 0.f;

        #pragma unroll
        for (int kt = 0; kt < 4; ++kt) {
            uint32_t ah[4], al_[4];
            ah[0]  = *(const uint32_t*)&Qh[r0 * AST + 16 * kt + 2 * tig];
            ah[1]  = *(const uint32_t*)&Qh[(r0 + 8) * AST + 16 * kt + 2 * tig];
            ah[2]  = *(const uint32_t*)&Qh[r0 * AST + 16 * kt + 8 + 2 * tig];
            ah[3]  = *(const uint32_t*)&Qh[(r0 + 8) * AST + 16 * kt + 8 + 2 * tig];
            al_[0] = *(const uint32_t*)&Ql[r0 * AST + 16 * kt + 2 * tig];
            al_[1] = *(const uint32_t*)&Ql[(r0 + 8) * AST + 16 * kt + 2 * tig];
            al_[2] = *(const uint32_t*)&Ql[r0 * AST + 16 * kt + 8 + 2 * tig];
            al_[3] = *(const uint32_t*)&Ql[(r0 + 8) * AST + 16 * kt + 8 + 2 * tig];
            #pragma unroll
            for (int t = 0; t < 8; ++t) {
                const int n = 8 * t + g;      // kv col
                const uint32_t bh0 = *(const uint32_t*)&Kh[n * AST + 16 * kt + 2 * tig];
                const uint32_t bh1 = *(const uint32_t*)&Kh[n * AST + 16 * kt + 8 + 2 * tig];
                const uint32_t bl0 = *(const uint32_t*)&Kl[n * AST + 16 * kt + 2 * tig];
                const uint32_t bl1 = *(const uint32_t*)&Kl[n * AST + 16 * kt + 8 + 2 * tig];
                MMA_BF16(S[t], ah, bh0, bh1);
                MMA_BF16(S[t], ah, bl0, bl1);
                MMA_BF16(S[t], al_, bh0, bh1);
            }
        }

        // ---- scale + causal mask ----
        const bool need_mask = (k0 + 64 > TP_ + q0);
        #pragma unroll
        for (int t = 0; t < 8; ++t)
            #pragma unroll
            for (int fr = 0; fr < 4; ++fr) {
                const int i = q0 + r0 + (fr >> 1) * 8;
                const int j = k0 + 8 * t + 2 * tig + (fr & 1);
                float v = S[t][fr] * 0.125f;
                if (need_mask && (j > TP_ + i)) v = -1e30f;
                S[t][fr] = v;
            }

        // ---- online softmax (rows r0 and r0+8) ----
        float mx0 = -1e30f, mx1 = -1e30f;
        #pragma unroll
        for (int t = 0; t < 8; ++t) {
            mx0 = fmaxf(mx0, fmaxf(S[t][0], S[t][1]));
            mx1 = fmaxf(mx1, fmaxf(S[t][2], S[t][3]));
        }
        mx0 = fmaxf(mx0, __shfl_xor_sync(0xffffffffu, mx0, 1));
        mx0 = fmaxf(mx0, __shfl_xor_sync(0xffffffffu, mx0, 2));
        mx1 = fmaxf(mx1, __shfl_xor_sync(0xffffffffu, mx1, 1));
        mx1 = fmaxf(mx1, __shfl_xor_sync(0xffffffffu, mx1, 2));
        const float mn0 = fmaxf(m0, mx0), mn1 = fmaxf(m1, mx1);
        const float cr0 = __expf(m0 - mn0), cr1 = __expf(m1 - mn1);
        m0 = mn0; m1 = mn1;
        float ls0 = 0.f, ls1 = 0.f;
        #pragma unroll
        for (int t = 0; t < 8; ++t) {
            S[t][0] = __expf(S[t][0] - mn0); ls0 += S[t][0];
            S[t][1] = __expf(S[t][1] - mn0); ls0 += S[t][1];
            S[t][2] = __expf(S[t][2] - mn1); ls1 += S[t][2];
            S[t][3] = __expf(S[t][3] - mn1); ls1 += S[t][3];
        }
        ls0 += __shfl_xor_sync(0xffffffffu, ls0, 1);
        ls0 += __shfl_xor_sync(0xffffffffu, ls0, 2);
        ls1 += __shfl_xor_sync(0xffffffffu, ls1, 1);
        ls1 += __shfl_xor_sync(0xffffffffu, ls1, 2);
        l0 = l0 * cr0 + ls0;
        l1 = l1 * cr1 + ls1;
        #pragma unroll
        for (int t = 0; t < 8; ++t) {
            O[t][0] *= cr0; O[t][1] *= cr0;
            O[t][2] *= cr1; O[t][3] *= cr1;
        }

        // ---- O += P V (P packed from S frags; hi/lo split) ----
        #pragma unroll
        for (int kt = 0; kt < 4; ++kt) {
            uint32_t ph[4], pl[4];
            ph[0] = bfpack(S[2 * kt][0], S[2 * kt][1]);
            ph[1] = bfpack(S[2 * kt][2], S[2 * kt][3]);
            ph[2] = bfpack(S[2 * kt + 1][0], S[2 * kt + 1][1]);
            ph[3] = bfpack(S[2 * kt + 1][2], S[2 * kt + 1][3]);
            pl[0] = bfpack(S[2 * kt][0] - bflo_f(ph[0]), S[2 * kt][1] - bfhi_f(ph[0]));
            pl[1] = bfpack(S[2 * kt][2] - bflo_f(ph[1]), S[2 * kt][3] - bfhi_f(ph[1]));
            pl[2] = bfpack(S[2 * kt + 1][0] - bflo_f(ph[2]), S[2 * kt + 1][1] - bfhi_f(ph[2]));
            pl[3] = bfpack(S[2 * kt + 1][2] - bflo_f(ph[3]), S[2 * kt + 1][3] - bfhi_f(ph[3]));
            #pragma unroll
            for (int t = 0; t < 8; ++t) {
                const int dn = 8 * t + g;     // d col
                const uint32_t bh0 = *(const uint32_t*)&Vth[dn * AST + 16 * kt + 2 * tig];
                const uint32_t bh1 = *(const uint32_t*)&Vth[dn * AST + 16 * kt + 8 + 2 * tig];
                const uint32_t bl0 = *(const uint32_t*)&Vtl[dn * AST + 16 * kt + 2 * tig];
                const uint32_t bl1 = *(const uint32_t*)&Vtl[dn * AST + 16 * kt + 8 + 2 * tig];
                MMA_BF16(O[t], ph, bh0, bh1);
                MMA_BF16(O[t], ph, bl0, bl1);
                MMA_BF16(O[t], pl, bh0, bh1);
            }
        }
    }

    // ---- epilogue: normalize, write to g_attn [B,TQ,DM] ----
    const int bb = bh >> 4, hh = bh & 15;
    const float inv0 = 1.f / l0, inv1 = 1.f / l1;
    #pragma unroll
    for (int t = 0; t < 8; ++t) {
        const int dcol = hh * 64 + 8 * t + 2 * tig;
        float2 w0 = {O[t][0] * inv0, O[t][1] * inv0};
        float2 w1 = {O[t][2] * inv1, O[t][3] * inv1};
        *(float2*)&g_attn[((size_t)bb * TQ_ + q0 + r0) * DM_ + dcol] = w0;
        *(float2*)&g_attn[((size_t)bb * TQ_ + q0 + r0 + 8) * DM_ + dcol] = w1;
    }
}

// ---------------------------------------------------------------------------
extern "C" void kernel_launch(void* const* d_in, const int* in_sizes, int n_in,
                              void* d_out, int out_size)
{
    const float* query = (const float*)d_in[0];
    const float* key   = (const float*)d_in[1];
    const float* value = (const float*)d_in[2];
    const float* pastK = (const float*)d_in[3];
    const float* pastV = (const float*)d_in[4];
    const float* Wq = (const float*)d_in[6];
    const float* bq = (const float*)d_in[7];
    const float* Wk = (const float*)d_in[8];
    const float* bk = (const float*)d_in[9];
    const float* Wv = (const float*)d_in[10];
    const float* bv = (const float*)d_in[11];
    const float* Wo = (const float*)d_in[12];
    const float* bo = (const float*)d_in[13];

    float* out  = (float*)d_out;
    float* outK = out + (size_t)B_ * TQ_ * DM_;
    float* outV = outK + (size_t)B_ * H_ * TKV_ * DK_;

    cudaFuncSetAttribute(attn_mma_kernel,
                         cudaFuncAttributeMaxDynamicSharedMemorySize, AT_SMEM);

    dim3 gg(DM_ / 128, (B_ * TQ_) / 128);  // (8, 32)
    gemm_mma_kernel<<<gg, 256>>>(query, Wq, bq, nullptr, 0);
    gemm_mma_kernel<<<gg, 256>>>(key,   Wk, bk, outK,   1);
    gemm_mma_kernel<<<gg, 256>>>(value, Wv, bv, outV,   2);
    copy_past_kernel<<<1024, 256>>>((const float4*)pastK, (const float4*)pastV,
                                    (float4*)outK, (float4*)outV);
    attn_mma_kernel<<<dim3(TQ_ / 64, B_ * H_), 128, AT_SMEM>>>(outK, outV);
    gemm_mma_kernel<<<gg, 256>>>(nullptr, Wo, bo, out, 3);
}